// round 1
// baseline (speedup 1.0000x reference)
#include <cuda_runtime.h>

// ActionSmoothingLoss: segmented log-softmax KL divergence
// NVEC = (3,3,4,25,25,8), A = 68, W = 524288

#define A_DIM 68
#define NSEG 6
#define BLOCK 256

__device__ double g_acc;

__global__ void asl_zero_kernel() {
    g_acc = 0.0;
}

__global__ void __launch_bounds__(BLOCK) asl_main_kernel(
    const float* __restrict__ cur,
    const float* __restrict__ prev,
    int W)
{
    __shared__ float xs[A_DIM];
    __shared__ double sred[BLOCK];

    const int tid = threadIdx.x;

    // --- Stage 1: load current_action into smem ---
    if (tid < A_DIM) xs[tid] = cur[tid];
    __syncthreads();

    // --- Stage 2: segmented log_softmax of current_action (6 threads, one per segment) ---
    if (tid < NSEG) {
        const int off[NSEG] = {0, 3, 6, 10, 35, 60};
        const int sz[NSEG]  = {3, 3, 4, 25, 25, 8};
        const int o = off[tid];
        const int n = sz[tid];
        float s = 0.f;
        for (int i = 0; i < n; i++) s += __expf(xs[o + i]);
        const float L = __logf(s);
        for (int i = 0; i < n; i++) xs[o + i] -= L;
    }
    __syncthreads();

    // --- Stage 3: one thread per row ---
    const int w = blockIdx.x * BLOCK + tid;
    float row_loss = 0.f;

    if (w < W) {
        // Row is 68 floats = 17 float4 (272 B, 16B-aligned for every row).
        const float4* rp = reinterpret_cast<const float4*>(prev + (size_t)w * A_DIM);
        float r[A_DIM];
        #pragma unroll
        for (int i = 0; i < 17; i++) {
            float4 v = rp[i];
            r[4*i + 0] = v.x;
            r[4*i + 1] = v.y;
            r[4*i + 2] = v.z;
            r[4*i + 3] = v.w;
        }

        const int   off[NSEG]  = {0, 3, 6, 10, 35, 60};
        const int   sz[NSEG]   = {3, 3, 4, 25, 25, 8};
        const float invn[NSEG] = {1.f/3.f, 1.f/3.f, 1.f/4.f, 1.f/25.f, 1.f/25.f, 1.f/8.f};

        #pragma unroll
        for (int j = 0; j < NSEG; j++) {
            const int o = off[j];
            const int n = sz[j];
            float s   = 0.f;   // sum exp(r)
            float acc = 0.f;   // sum exp(r) * (r - x)
            #pragma unroll
            for (int i = 0; i < n; i++) {
                const float ri = r[o + i];
                const float e  = __expf(ri);
                s   += e;
                acc += e * (ri - xs[o + i]);
            }
            // segment loss: sum_i p_i*(t_i - x_i) = acc/s - log(s)
            row_loss += invn[j] * (__fdividef(acc, s) - __logf(s));
        }
    }

    // --- Stage 4: block reduction in double, one atomic per block ---
    sred[tid] = (double)row_loss;
    __syncthreads();
    #pragma unroll
    for (int st = BLOCK / 2; st > 0; st >>= 1) {
        if (tid < st) sred[tid] += sred[tid + st];
        __syncthreads();
    }
    if (tid == 0) atomicAdd(&g_acc, sred[0]);
}

__global__ void asl_final_kernel(float* __restrict__ out, double invW) {
    out[0] = (float)(g_acc * invW);
}

extern "C" void kernel_launch(void* const* d_in, const int* in_sizes, int n_in,
                              void* d_out, int out_size)
{
    const float* cur  = (const float*)d_in[0];   // [68]
    const float* prev = (const float*)d_in[1];   // [W, 68]
    const int W = in_sizes[1] / A_DIM;

    float* out = (float*)d_out;

    asl_zero_kernel<<<1, 1>>>();
    const int grid = (W + BLOCK - 1) / BLOCK;
    asl_main_kernel<<<grid, BLOCK>>>(cur, prev, W);
    asl_final_kernel<<<1, 1>>>(out, 1.0 / (double)W);
}

// round 2
// speedup vs baseline: 1.6673x; 1.6673x over previous
#include <cuda_runtime.h>

// ActionSmoothingLoss: segmented log-softmax KL divergence
// NVEC = (3,3,4,25,25,8), A = 68, W = 524288
// Single-launch threadfence-reduction version.

#define A_DIM 68
#define NSEG 6
#define BLOCK 256
#define MAX_BLOCKS 8192

__device__ double g_part[MAX_BLOCKS];
__device__ unsigned int g_count = 0;   // always returns to 0 -> graph-replay safe

// static element -> segment map (offsets 0,3,6,10,35,60)
#define SEG_OF(k) ((k) < 3 ? 0 : (k) < 6 ? 1 : (k) < 10 ? 2 : (k) < 35 ? 3 : (k) < 60 ? 4 : 5)

__global__ void __launch_bounds__(BLOCK) asl_kernel(
    const float* __restrict__ cur,
    const float* __restrict__ prev,
    float* __restrict__ out,
    int W, int nblocks)
{
    __shared__ float xs[A_DIM];
    __shared__ double wred[BLOCK / 32];
    __shared__ bool is_last;

    const int tid = threadIdx.x;

    // --- current_action log-softmax into smem (cheap, per block) ---
    if (tid < A_DIM) xs[tid] = cur[tid];
    __syncthreads();
    if (tid < NSEG) {
        const int off[NSEG] = {0, 3, 6, 10, 35, 60};
        const int sz[NSEG]  = {3, 3, 4, 25, 25, 8};
        const int o = off[tid], n = sz[tid];
        float s = 0.f;
        for (int i = 0; i < n; i++) s += __expf(xs[o + i]);
        const float L = __logf(s);
        for (int i = 0; i < n; i++) xs[o + i] -= L;
    }
    __syncthreads();

    // --- one thread per row, streaming segment accumulators ---
    const int w = blockIdx.x * BLOCK + tid;
    float row_loss = 0.f;

    if (w < W) {
        const float4* rp = reinterpret_cast<const float4*>(prev + (size_t)w * A_DIM);
        float s[NSEG]   = {0.f, 0.f, 0.f, 0.f, 0.f, 0.f};
        float acc[NSEG] = {0.f, 0.f, 0.f, 0.f, 0.f, 0.f};

        #pragma unroll
        for (int i = 0; i < 17; i++) {
            const float4 v = rp[i];
            const float vv[4] = {v.x, v.y, v.z, v.w};
            #pragma unroll
            for (int k = 0; k < 4; k++) {
                const int idx = 4 * i + k;
                const int j = SEG_OF(idx);           // compile-time constant
                const float r = vv[k];
                const float e = __expf(r);
                s[j]   += e;
                acc[j] += e * (r - xs[idx]);
            }
        }

        const float invn[NSEG] = {1.f/3.f, 1.f/3.f, 1.f/4.f, 1.f/25.f, 1.f/25.f, 1.f/8.f};
        #pragma unroll
        for (int j = 0; j < NSEG; j++)
            row_loss += invn[j] * (__fdividef(acc[j], s[j]) - __logf(s[j]));
    }

    // --- block reduction: warp shuffle (double), then cross-warp via smem ---
    double d = (double)row_loss;
    #pragma unroll
    for (int st = 16; st > 0; st >>= 1)
        d += __shfl_down_sync(0xFFFFFFFFu, d, st);
    if ((tid & 31) == 0) wred[tid >> 5] = d;
    __syncthreads();
    if (tid == 0) {
        double b = 0.0;
        #pragma unroll
        for (int k = 0; k < BLOCK / 32; k++) b += wred[k];
        g_part[blockIdx.x] = b;
        __threadfence();
        unsigned int t = atomicAdd(&g_count, 1u);
        is_last = (t == (unsigned int)(nblocks - 1));
    }
    __syncthreads();

    // --- last block reduces all partials, writes output, resets counter ---
    if (is_last) {
        double acc2 = 0.0;
        for (int k = tid; k < nblocks; k += BLOCK) acc2 += g_part[k];
        #pragma unroll
        for (int st = 16; st > 0; st >>= 1)
            acc2 += __shfl_down_sync(0xFFFFFFFFu, acc2, st);
        if ((tid & 31) == 0) wred[tid >> 5] = acc2;
        __syncthreads();
        if (tid == 0) {
            double tot = 0.0;
            #pragma unroll
            for (int k = 0; k < BLOCK / 32; k++) tot += wred[k];
            out[0] = (float)(tot / (double)W);
            g_count = 0;   // reset for next graph replay
        }
    }
}

extern "C" void kernel_launch(void* const* d_in, const int* in_sizes, int n_in,
                              void* d_out, int out_size)
{
    const float* cur  = (const float*)d_in[0];   // [68]
    const float* prev = (const float*)d_in[1];   // [W, 68]
    const int W = in_sizes[1] / A_DIM;
    const int nblocks = (W + BLOCK - 1) / BLOCK;

    asl_kernel<<<nblocks, BLOCK>>>(cur, prev, (float*)d_out, W, nblocks);
}

// round 3
// speedup vs baseline: 1.7968x; 1.0777x over previous
#include <cuda_runtime.h>

// ActionSmoothingLoss: segmented log-softmax KL divergence
// NVEC = (3,3,4,25,25,8), A = 68, W = 524288
// Coalesced smem-staged version, single launch.

#define A_DIM   68
#define NSEG    6
#define BLOCK   128
#define TILE    128              // rows per block (== BLOCK, one row per thread)
#define PITCH   69               // words per row in smem (69 mod 32 = 5, conflict-free)
#define F4_PER_TILE (TILE * 17)  // 2176 float4 per tile
#define MAX_BLOCKS 8192

__device__ double g_part[MAX_BLOCKS];
__device__ unsigned int g_count = 0;   // returns to 0 every call -> graph-replay safe

#define SEG_OF(k) ((k) < 3 ? 0 : (k) < 6 ? 1 : (k) < 10 ? 2 : (k) < 35 ? 3 : (k) < 60 ? 4 : 5)

__global__ void __launch_bounds__(BLOCK, 6) asl_kernel(
    const float* __restrict__ cur,
    const float* __restrict__ prev,
    float* __restrict__ out,
    int W, int nblocks)
{
    __shared__ float sdata[TILE * PITCH];    // 128 * 69 * 4 = 35328 B
    __shared__ float xs[A_DIM];
    __shared__ double wred[BLOCK / 32];
    __shared__ bool is_last;

    const int tid = threadIdx.x;

    // --- current_action log-softmax into smem ---
    if (tid < A_DIM) xs[tid] = cur[tid];
    __syncthreads();
    if (tid < NSEG) {
        const int off[NSEG] = {0, 3, 6, 10, 35, 60};
        const int sz[NSEG]  = {3, 3, 4, 25, 25, 8};
        const int o = off[tid], n = sz[tid];
        float s = 0.f;
        for (int i = 0; i < n; i++) s += __expf(xs[o + i]);
        const float L = __logf(s);
        for (int i = 0; i < n; i++) xs[o + i] -= L;
    }
    __syncthreads();

    // --- Stage tile: coalesced float4 global loads -> pitch-69 smem rows ---
    {
        const size_t tile_f4_base = (size_t)blockIdx.x * F4_PER_TILE;
        const float4* gp = reinterpret_cast<const float4*>(prev) + tile_f4_base;
        const size_t total_f4 = ((size_t)W * A_DIM) / 4;
        #pragma unroll
        for (int k = 0; k < 17; k++) {
            const int idx = tid + k * BLOCK;            // 0..2175
            if (tile_f4_base + idx < total_f4) {
                const float4 v = gp[idx];
                const int r = idx / 17;
                const int c = (idx % 17) * 4;
                float* dst = &sdata[r * PITCH + c];
                dst[0] = v.x; dst[1] = v.y; dst[2] = v.z; dst[3] = v.w;
            }
        }
    }
    __syncthreads();

    // --- Compute: one thread per row from smem (conflict-free: 69 mod 32 = 5) ---
    const int w = blockIdx.x * TILE + tid;
    float row_loss = 0.f;

    if (w < W) {
        const float* row = &sdata[tid * PITCH];
        float s[NSEG]   = {0.f, 0.f, 0.f, 0.f, 0.f, 0.f};
        float acc[NSEG] = {0.f, 0.f, 0.f, 0.f, 0.f, 0.f};

        #pragma unroll
        for (int i = 0; i < A_DIM; i++) {
            const int j = SEG_OF(i);          // compile-time constant
            const float ri = row[i];
            const float e  = __expf(ri);
            s[j]   += e;
            acc[j] += e * (ri - xs[i]);
        }

        const float invn[NSEG] = {1.f/3.f, 1.f/3.f, 1.f/4.f, 1.f/25.f, 1.f/25.f, 1.f/8.f};
        #pragma unroll
        for (int j = 0; j < NSEG; j++)
            row_loss += invn[j] * (__fdividef(acc[j], s[j]) - __logf(s[j]));
    }

    // --- Block reduction (double), deterministic ---
    double d = (double)row_loss;
    #pragma unroll
    for (int st = 16; st > 0; st >>= 1)
        d += __shfl_down_sync(0xFFFFFFFFu, d, st);
    if ((tid & 31) == 0) wred[tid >> 5] = d;
    __syncthreads();
    if (tid == 0) {
        double b = 0.0;
        #pragma unroll
        for (int k = 0; k < BLOCK / 32; k++) b += wred[k];
        g_part[blockIdx.x] = b;
        __threadfence();
        unsigned int t = atomicAdd(&g_count, 1u);
        is_last = (t == (unsigned int)(nblocks - 1));
    }
    __syncthreads();

    // --- Last block: reduce partials in fixed order, write out, reset counter ---
    if (is_last) {
        double acc2 = 0.0;
        for (int k = tid; k < nblocks; k += BLOCK) acc2 += g_part[k];
        #pragma unroll
        for (int st = 16; st > 0; st >>= 1)
            acc2 += __shfl_down_sync(0xFFFFFFFFu, acc2, st);
        if ((tid & 31) == 0) wred[tid >> 5] = acc2;
        __syncthreads();
        if (tid == 0) {
            double tot = 0.0;
            #pragma unroll
            for (int k = 0; k < BLOCK / 32; k++) tot += wred[k];
            out[0] = (float)(tot / (double)W);
            g_count = 0;
        }
    }
}

extern "C" void kernel_launch(void* const* d_in, const int* in_sizes, int n_in,
                              void* d_out, int out_size)
{
    const float* cur  = (const float*)d_in[0];   // [68]
    const float* prev = (const float*)d_in[1];   // [W, 68]
    const int W = in_sizes[1] / A_DIM;
    const int nblocks = (W + TILE - 1) / TILE;

    asl_kernel<<<nblocks, BLOCK>>>(cur, prev, (float*)d_out, W, nblocks);
}

// round 4
// speedup vs baseline: 2.6489x; 1.4742x over previous
#include <cuda_runtime.h>
#include <cstdint>

// ActionSmoothingLoss: segmented log-softmax KL divergence
// NVEC = (3,3,4,25,25,8), A = 68, W = 524288
// cp.async double-buffered pipeline, linear smem tiles, LDS.128 reads.

#define A_DIM      68
#define NSEG       6
#define BLOCK      64
#define TILE       64                    // rows per tile (1 row per thread)
#define F4_ROW     17
#define F4_TILE    (TILE * F4_ROW)       // 1088 float4 per tile
#define MAX_BLOCKS 1024

__device__ double g_part[MAX_BLOCKS];
__device__ unsigned int g_count = 0;     // returns to 0 each call -> graph-replay safe

#define SEG_OF(k) ((k) < 3 ? 0 : (k) < 6 ? 1 : (k) < 10 ? 2 : (k) < 35 ? 3 : (k) < 60 ? 4 : 5)

__device__ __forceinline__ void cp16(uint32_t dst_smem, const void* src, int bytes) {
    asm volatile("cp.async.cg.shared.global [%0], [%1], 16, %2;\n"
                 :: "r"(dst_smem), "l"(src), "r"(bytes));
}
__device__ __forceinline__ void cp_commit() { asm volatile("cp.async.commit_group;\n"); }
__device__ __forceinline__ void cp_wait1()  { asm volatile("cp.async.wait_group 1;\n" ::: "memory"); }
__device__ __forceinline__ void cp_wait0()  { asm volatile("cp.async.wait_group 0;\n" ::: "memory"); }

__global__ void __launch_bounds__(BLOCK) asl_kernel(
    const float* __restrict__ cur,
    const float* __restrict__ prev,
    float* __restrict__ out,
    int W, int ntiles, int nblocks)
{
    __shared__ float sdata[2][F4_TILE * 4];   // 2 x 17408 B = 34816 B, linear tile copy
    __shared__ float xs[A_DIM];
    __shared__ double wred[BLOCK / 32];
    __shared__ bool is_last;

    const int tid = threadIdx.x;

    // --- current_action segmented log-softmax (once per block) ---
    for (int i = tid; i < A_DIM; i += BLOCK) xs[i] = cur[i];
    __syncthreads();
    if (tid < NSEG) {
        const int off[NSEG] = {0, 3, 6, 10, 35, 60};
        const int sz[NSEG]  = {3, 3, 4, 25, 25, 8};
        const int o = off[tid], n = sz[tid];
        float s = 0.f;
        for (int i = 0; i < n; i++) s += __expf(xs[o + i]);
        const float L = __logf(s);
        for (int i = 0; i < n; i++) xs[o + i] -= L;
    }
    __syncthreads();

    const size_t total_f4 = ((size_t)W * A_DIM) >> 2;
    const float4* gp = reinterpret_cast<const float4*>(prev);

    const uint32_t sbase0 = (uint32_t)__cvta_generic_to_shared(&sdata[0][0]);
    const uint32_t sbase1 = (uint32_t)__cvta_generic_to_shared(&sdata[1][0]);

    // Stage tile -> buffer via cp.async (coalesced: warp covers 512 B contiguous)
    auto stage = [&](int tile, uint32_t sbase) {
        const size_t base = (size_t)tile * F4_TILE;
        #pragma unroll
        for (int k = 0; k < F4_ROW; k++) {
            const int idx = tid + k * BLOCK;                  // 0..1087
            const size_t g = base + idx;
            cp16(sbase + (uint32_t)idx * 16, gp + g, (g < total_f4) ? 16 : 0);
        }
        cp_commit();
    };

    double acc_d = 0.0;   // per-thread accumulator across tiles (fixed order)

    int tile = blockIdx.x;
    if (tile < ntiles) stage(tile, sbase0);   // prologue
    int buf = 0;

    for (; tile < ntiles; tile += nblocks) {
        const int next = tile + nblocks;
        if (next < ntiles) {
            stage(next, buf ? sbase0 : sbase1);
            cp_wait1();
        } else {
            cp_wait0();
        }
        __syncthreads();

        // --- Compute: one thread per row, 17 x LDS.128 (conflict-free) ---
        const int w = tile * TILE + tid;
        if (w < W) {
            const float4* row = reinterpret_cast<const float4*>(&sdata[buf][tid * A_DIM]);
            float s[NSEG]   = {0.f, 0.f, 0.f, 0.f, 0.f, 0.f};
            float acc[NSEG] = {0.f, 0.f, 0.f, 0.f, 0.f, 0.f};

            #pragma unroll
            for (int i = 0; i < F4_ROW; i++) {
                const float4 v = row[i];
                const float vv[4] = {v.x, v.y, v.z, v.w};
                #pragma unroll
                for (int c = 0; c < 4; c++) {
                    const int idx = 4 * i + c;
                    const int j = SEG_OF(idx);         // compile-time constant
                    const float r = vv[c];
                    const float e = __expf(r);
                    s[j]   += e;
                    acc[j] += e * (r - xs[idx]);
                }
            }

            const float invn[NSEG] = {1.f/3.f, 1.f/3.f, 1.f/4.f, 1.f/25.f, 1.f/25.f, 1.f/8.f};
            float row_loss = 0.f;
            #pragma unroll
            for (int j = 0; j < NSEG; j++)
                row_loss += invn[j] * (__fdividef(acc[j], s[j]) - __logf(s[j]));
            acc_d += (double)row_loss;
        }
        __syncthreads();   // everyone done reading buf before it is re-staged
        buf ^= 1;
    }

    // --- Block reduction (double), deterministic ---
    double d = acc_d;
    #pragma unroll
    for (int st = 16; st > 0; st >>= 1)
        d += __shfl_down_sync(0xFFFFFFFFu, d, st);
    if ((tid & 31) == 0) wred[tid >> 5] = d;
    __syncthreads();
    if (tid == 0) {
        double b = 0.0;
        #pragma unroll
        for (int k = 0; k < BLOCK / 32; k++) b += wred[k];
        g_part[blockIdx.x] = b;
        __threadfence();
        unsigned int t = atomicAdd(&g_count, 1u);
        is_last = (t == (unsigned int)(nblocks - 1));
    }
    __syncthreads();

    // --- Last block: reduce all partials (fixed order), write out, reset ---
    if (is_last) {
        double a2 = 0.0;
        for (int k = tid; k < nblocks; k += BLOCK) a2 += g_part[k];
        #pragma unroll
        for (int st = 16; st > 0; st >>= 1)
            a2 += __shfl_down_sync(0xFFFFFFFFu, a2, st);
        if ((tid & 31) == 0) wred[tid >> 5] = a2;
        __syncthreads();
        if (tid == 0) {
            double tot = 0.0;
            #pragma unroll
            for (int k = 0; k < BLOCK / 32; k++) tot += wred[k];
            out[0] = (float)(tot / (double)W);
            g_count = 0;
        }
    }
}

extern "C" void kernel_launch(void* const* d_in, const int* in_sizes, int n_in,
                              void* d_out, int out_size)
{
    const float* cur  = (const float*)d_in[0];   // [68]
    const float* prev = (const float*)d_in[1];   // [W, 68]
    const int W = in_sizes[1] / A_DIM;
    const int ntiles = (W + TILE - 1) / TILE;

    int nblocks = 148 * 6;                       // 6 resident blocks/SM (smem-limited)
    if (nblocks > ntiles) nblocks = ntiles;
    if (nblocks > MAX_BLOCKS) nblocks = MAX_BLOCKS;

    asl_kernel<<<nblocks, BLOCK>>>(cur, prev, (float*)d_out, W, ntiles, nblocks);
}

// round 6
// speedup vs baseline: 2.6514x; 1.0010x over previous
#include <cuda_runtime.h>
#include <cstdint>

// ActionSmoothingLoss: segmented log-softmax KL
// NVEC = (3,3,4,25,25,8), A = 68, W = 524288
// cp.async double-buffered pipeline; 4 threads per row (warp-uniform quarters).

#define A_DIM      68
#define NSEG       6
#define BLOCK      256
#define TILE       64                    // rows per tile
#define F4_ROW     17
#define F4_TILE    (TILE * F4_ROW)       // 1088 float4 per tile
#define PSTRIDE    20                    // floats per row in partial buffer
#define MAX_BLOCKS 1024

__device__ double g_part[MAX_BLOCKS];
__device__ unsigned int g_count = 0;     // returns to 0 each call -> graph-replay safe

#define SEG_OF(k) ((k) < 3 ? 0 : (k) < 6 ? 1 : (k) < 10 ? 2 : (k) < 35 ? 3 : (k) < 60 ? 4 : 5)

__device__ __forceinline__ void cp16(uint32_t dst_smem, const void* src, int bytes) {
    asm volatile("cp.async.cg.shared.global [%0], [%1], 16, %2;\n"
                 :: "r"(dst_smem), "l"(src), "r"(bytes));
}
__device__ __forceinline__ void cp_commit() { asm volatile("cp.async.commit_group;\n"); }
__device__ __forceinline__ void cp_wait1()  { asm volatile("cp.async.wait_group 1;\n" ::: "memory"); }
__device__ __forceinline__ void cp_wait0()  { asm volatile("cp.async.wait_group 0;\n" ::: "memory"); }

// Process f4 indices [F0, F0+NF4) of one row; accumulate into s[6]/a[6]
// (only compile-time-touched slots stay live in registers).
template<int F0, int NF4>
__device__ __forceinline__ void quarter_accum(const float* __restrict__ row,
                                              const float* __restrict__ xs,
                                              float* s, float* a)
{
    const float4* rp = reinterpret_cast<const float4*>(row);
    #pragma unroll
    for (int i = 0; i < NF4; i++) {
        const float4 v = rp[F0 + i];
        const float vv[4] = {v.x, v.y, v.z, v.w};
        #pragma unroll
        for (int c = 0; c < 4; c++) {
            const int idx = (F0 + i) * 4 + c;
            const int j = SEG_OF(idx);
            const float r = vv[c];
            const float e = __expf(r);
            s[j] += e;
            a[j] += e * (r - xs[idx]);
        }
    }
}

__global__ void __launch_bounds__(BLOCK, 5) asl_kernel(
    const float* __restrict__ cur,
    const float* __restrict__ prev,
    float* __restrict__ out,
    int W, int ntiles, int nblocks)
{
    __shared__ float sdata[2][F4_TILE * 4];     // 2 x 17408 B
    __shared__ float part[TILE * PSTRIDE];      // 5120 B quarter partials
    __shared__ float xs[A_DIM];
    __shared__ double wred[BLOCK / 32];
    __shared__ bool is_last;

    const int tid = threadIdx.x;
    const int q   = tid >> 6;          // quarter index, uniform per warp-pair
    const int row = tid & 63;          // row within tile

    // --- current_action segmented log-softmax ---
    if (tid < A_DIM) xs[tid] = cur[tid];
    __syncthreads();
    if (tid < NSEG) {
        const int off[NSEG] = {0, 3, 6, 10, 35, 60};
        const int sz[NSEG]  = {3, 3, 4, 25, 25, 8};
        const int o = off[tid], n = sz[tid];
        float s = 0.f;
        for (int i = 0; i < n; i++) s += __expf(xs[o + i]);
        const float L = __logf(s);
        for (int i = 0; i < n; i++) xs[o + i] -= L;
    }
    __syncthreads();

    const size_t total_f4 = ((size_t)W * A_DIM) >> 2;
    const float4* gp = reinterpret_cast<const float4*>(prev);
    const uint32_t sbase0 = (uint32_t)__cvta_generic_to_shared(&sdata[0][0]);
    const uint32_t sbase1 = (uint32_t)__cvta_generic_to_shared(&sdata[1][0]);

    auto stage = [&](int tile, uint32_t sbase) {
        const size_t base = (size_t)tile * F4_TILE;
        #pragma unroll
        for (int k = 0; k < 4; k++) {
            const int idx = tid + k * BLOCK;
            const size_t g = base + idx;
            cp16(sbase + (uint32_t)idx * 16, gp + g, (g < total_f4) ? 16 : 0);
        }
        if (tid < F4_TILE - 4 * BLOCK) {                 // remaining 64
            const int idx = tid + 4 * BLOCK;
            const size_t g = base + idx;
            cp16(sbase + (uint32_t)idx * 16, gp + g, (g < total_f4) ? 16 : 0);
        }
        cp_commit();
    };

    double acc_d = 0.0;

    int tile = blockIdx.x;
    if (tile < ntiles) stage(tile, sbase0);
    int buf = 0;

    for (; tile < ntiles; tile += nblocks) {
        const int next = tile + nblocks;
        if (next < ntiles) { stage(next, buf ? sbase0 : sbase1); cp_wait1(); }
        else               { cp_wait0(); }
        __syncthreads();

        // --- per-quarter accumulation (warp-uniform branch) ---
        const float* rdata = &sdata[buf][row * A_DIM];
        float s[NSEG] = {0,0,0,0,0,0};
        float a[NSEG] = {0,0,0,0,0,0};
        float* pr = &part[row * PSTRIDE];

        if (q == 0) {                       // elements 0..15: segs 0,1,2,3p
            quarter_accum<0, 4>(rdata, xs, s, a);
            pr[0] = s[0]; pr[1] = s[1]; pr[2] = s[2]; pr[3] = s[3];
            pr[4] = a[0]; pr[5] = a[1]; pr[6] = a[2]; pr[7] = a[3];
        } else if (q == 1) {                // elements 16..31: seg 3p
            quarter_accum<4, 4>(rdata, xs, s, a);
            pr[8] = s[3]; pr[9] = a[3];
        } else if (q == 2) {                // elements 32..47: segs 3p,4p
            quarter_accum<8, 4>(rdata, xs, s, a);
            pr[10] = s[3]; pr[11] = s[4]; pr[12] = a[3]; pr[13] = a[4];
        } else {                            // elements 48..67: segs 4p,5
            quarter_accum<12, 5>(rdata, xs, s, a);
            pr[14] = s[4]; pr[15] = s[5]; pr[16] = a[4]; pr[17] = a[5];
        }
        __syncthreads();    // partials visible; all reads of buf done

        // --- finalize: threads 0..63 stitch segments, compute row loss ---
        const int w = tile * TILE + row;
        if (tid < TILE && w < W) {
            const float* p = &part[tid * PSTRIDE];
            const float fs[NSEG] = {p[0], p[1], p[2],
                                    p[3] + p[8] + p[10],
                                    p[11] + p[14],
                                    p[15]};
            const float fa[NSEG] = {p[4], p[5], p[6],
                                    p[7] + p[9] + p[12],
                                    p[13] + p[16],
                                    p[17]};
            const float invn[NSEG] = {1.f/3.f, 1.f/3.f, 1.f/4.f, 1.f/25.f, 1.f/25.f, 1.f/8.f};
            float row_loss = 0.f;
            #pragma unroll
            for (int j = 0; j < NSEG; j++)
                row_loss += invn[j] * (__fdividef(fa[j], fs[j]) - __logf(fs[j]));
            acc_d += (double)row_loss;
        }
        __syncthreads();    // finalize done before partials/buf reused
        buf ^= 1;
    }

    // --- block reduction (double), deterministic ---
    double d = acc_d;
    #pragma unroll
    for (int st = 16; st > 0; st >>= 1)
        d += __shfl_down_sync(0xFFFFFFFFu, d, st);
    if ((tid & 31) == 0) wred[tid >> 5] = d;
    __syncthreads();
    if (tid == 0) {
        double b = 0.0;
        #pragma unroll
        for (int k = 0; k < BLOCK / 32; k++) b += wred[k];
        g_part[blockIdx.x] = b;
        __threadfence();
        unsigned int t = atomicAdd(&g_count, 1u);
        is_last = (t == (unsigned int)(nblocks - 1));
    }
    __syncthreads();

    if (is_last) {
        double a2 = 0.0;
        for (int k = tid; k < nblocks; k += BLOCK) a2 += g_part[k];
        #pragma unroll
        for (int st = 16; st > 0; st >>= 1)
            a2 += __shfl_down_sync(0xFFFFFFFFu, a2, st);
        if ((tid & 31) == 0) wred[tid >> 5] = a2;
        __syncthreads();
        if (tid == 0) {
            double tot = 0.0;
            #pragma unroll
            for (int k = 0; k < BLOCK / 32; k++) tot += wred[k];
            out[0] = (float)(tot / (double)W);
            g_count = 0;
        }
    }
}

extern "C" void kernel_launch(void* const* d_in, const int* in_sizes, int n_in,
                              void* d_out, int out_size)
{
    const float* cur  = (const float*)d_in[0];   // [68]
    const float* prev = (const float*)d_in[1];   // [W, 68]
    const int W = in_sizes[1] / A_DIM;
    const int ntiles = (W + TILE - 1) / TILE;

    int nblocks = 148 * 5;                       // 5 resident blocks/SM
    if (nblocks > ntiles) nblocks = ntiles;
    if (nblocks > MAX_BLOCKS) nblocks = MAX_BLOCKS;

    asl_kernel<<<nblocks, BLOCK>>>(cur, prev, (float*)d_out, W, ntiles, nblocks);
}